// round 4
// baseline (speedup 1.0000x reference)
#include <cuda_runtime.h>
#include <mma.h>
#include <cfloat>
#include <cstdint>

using namespace nvcuda;

#define L_  8
#define D_  1024
#define H_  16
#define T_  1024
#define V_  2048
#define B_  8
#define DH_ 64
#define FF_ 4096
#define M_  (B_ * T_)   // 8192 rows

// ---------------- scratch (device globals; no allocation allowed) -------------
__device__ float g_x [ (size_t)M_ * D_ ];
__device__ float g_h [ (size_t)M_ * D_ ];
__device__ float g_q [ (size_t)M_ * D_ ];
__device__ float g_k [ (size_t)M_ * D_ ];
__device__ float g_v [ (size_t)M_ * D_ ];
__device__ float g_o [ (size_t)M_ * D_ ];
__device__ float g_ff[ (size_t)M_ * FF_ ];
__device__ float g_s [ (size_t)B_ * H_ * T_ * T_ ];   // 512 MB attention scores

// ---------------- helpers ----------------------------------------------------
__device__ __forceinline__ float gelu_f(float x) {
    return 0.5f * x * (1.0f + erff(x * 0.70710678118654752f));
}

// =============================================================================
// Generic tiled GEMM, tf32 WMMA with 3-term fp32-emulation split.
//   C = A(MxK) * B(KxN) [+ bias] [+ gelu | + residual]
//   BT=true  : B is accessed transposed (B[k,n] = Bm[n*ldb + k])  (for Q K^T)
//   Batched via blockIdx.z with two-level (outer/inner) strides:
//       off = (z / innerDiv) * sOuter + (z % innerDiv) * sInner
// Assumes: M%BM==0, N%BN==0, K%BK==0 (true for every call here), 256 threads.
// =============================================================================
template<int BM, int BN, int BK, int WM, int WN, bool BT, int EPI>
__global__ __launch_bounds__(256)
void gemm_kernel(const float* __restrict__ A, const float* __restrict__ Bm,
                 const float* __restrict__ bias, const float* __restrict__ res,
                 float* __restrict__ C,
                 int M, int N, int K, int lda, int ldb, int ldc,
                 int innerDiv,
                 long long aOut, long long aIn,
                 long long bOut, long long bIn,
                 long long cOut, long long cIn)
{
    constexpr int MW    = BM / WM;        // warps along M
    constexpr int NW    = BN / WN;        // warps along N
    constexpr int NWARP = MW * NW;
    static_assert(NWARP == 8, "expect 256 threads");
    constexpr int LDA_S = BK + 4;
    constexpr int LDB_S = BN + 4;
    constexpr int LDS_T = WN + 4;
    constexpr int MI = WM / 16;
    constexpr int NI = WN / 16;

    __shared__ float sm[BM * LDA_S + BK * LDB_S];
    float* As = sm;
    float* Bs = sm + BM * LDA_S;

    const int z = blockIdx.z;
    const long long offA = (long long)(z / innerDiv) * aOut + (long long)(z % innerDiv) * aIn;
    const long long offB = (long long)(z / innerDiv) * bOut + (long long)(z % innerDiv) * bIn;
    const long long offC = (long long)(z / innerDiv) * cOut + (long long)(z % innerDiv) * cIn;
    A  += offA;
    Bm += offB;
    C  += offC;
    if constexpr (EPI == 2) res += offC;

    const int bm   = blockIdx.y * BM;
    const int bn   = blockIdx.x * BN;
    const int tid  = threadIdx.x;
    const int warp = tid >> 5;
    const int lane = tid & 31;
    const int wm   = (warp % MW) * WM;
    const int wn   = (warp / MW) * WN;

    wmma::fragment<wmma::accumulator, 16, 16, 8, float> acc[MI][NI];
    #pragma unroll
    for (int i = 0; i < MI; i++)
        #pragma unroll
        for (int j = 0; j < NI; j++)
            wmma::fill_fragment(acc[i][j], 0.0f);

    for (int k0 = 0; k0 < K; k0 += BK) {
        // ---- load A tile (BM x BK), row-major, float4 ----
        #pragma unroll
        for (int p = 0; p < BM / 32; ++p) {
            int r = p * 32 + (tid >> 3);
            int c = (tid & 7) * 4;
            float4 t4 = *reinterpret_cast<const float4*>(A + (long long)(bm + r) * lda + k0 + c);
            *reinterpret_cast<float4*>(&As[r * LDA_S + c]) = t4;
        }
        // ---- load B tile (BK x BN) ----
        if constexpr (!BT) {
            constexpr int F4R = BN / 4;          // float4 per row
            constexpr int RPP = 256 / F4R;       // rows per pass
            #pragma unroll
            for (int p = 0; p < BK / RPP; ++p) {
                int r = p * RPP + tid / F4R;
                int c = (tid % F4R) * 4;
                float4 t4 = *reinterpret_cast<const float4*>(Bm + (long long)(k0 + r) * ldb + bn + c);
                *reinterpret_cast<float4*>(&Bs[r * LDB_S + c]) = t4;
            }
        } else {
            // Bs[k][n] = Bm[(bn+n)*ldb + k0+k]  (transpose in-flight)
            constexpr int F4C = BK / 4;          // float4 along k per column
            constexpr int CPP = 256 / F4C;       // columns per pass
            #pragma unroll
            for (int p = 0; p < BN / CPP; ++p) {
                int n  = p * CPP + tid / F4C;
                int kk = (tid % F4C) * 4;
                float4 t4 = *reinterpret_cast<const float4*>(Bm + (long long)(bn + n) * ldb + k0 + kk);
                Bs[(kk + 0) * LDB_S + n] = t4.x;
                Bs[(kk + 1) * LDB_S + n] = t4.y;
                Bs[(kk + 2) * LDB_S + n] = t4.z;
                Bs[(kk + 3) * LDB_S + n] = t4.w;
            }
        }
        __syncthreads();

        #pragma unroll
        for (int kk = 0; kk < BK; kk += 8) {
            wmma::fragment<wmma::matrix_a, 16, 16, 8, wmma::precision::tf32, wmma::row_major> ahi[MI], alo[MI];
            wmma::fragment<wmma::matrix_b, 16, 16, 8, wmma::precision::tf32, wmma::row_major> bhi[NI], blo[NI];
            #pragma unroll
            for (int i = 0; i < MI; i++) {
                wmma::load_matrix_sync(ahi[i], &As[(wm + i * 16) * LDA_S + kk], LDA_S);
                #pragma unroll
                for (int e = 0; e < ahi[i].num_elements; e++) {
                    float f  = ahi[i].x[e];
                    float hi = wmma::__float_to_tf32(f);
                    ahi[i].x[e] = hi;
                    alo[i].x[e] = wmma::__float_to_tf32(f - hi);
                }
            }
            #pragma unroll
            for (int j = 0; j < NI; j++) {
                wmma::load_matrix_sync(bhi[j], &Bs[kk * LDB_S + wn + j * 16], LDB_S);
                #pragma unroll
                for (int e = 0; e < bhi[j].num_elements; e++) {
                    float f  = bhi[j].x[e];
                    float hi = wmma::__float_to_tf32(f);
                    bhi[j].x[e] = hi;
                    blo[j].x[e] = wmma::__float_to_tf32(f - hi);
                }
            }
            #pragma unroll
            for (int i = 0; i < MI; i++)
                #pragma unroll
                for (int j = 0; j < NI; j++) {
                    wmma::mma_sync(acc[i][j], ahi[i], bhi[j], acc[i][j]);
                    wmma::mma_sync(acc[i][j], alo[i], bhi[j], acc[i][j]);
                    wmma::mma_sync(acc[i][j], ahi[i], blo[j], acc[i][j]);
                }
        }
        __syncthreads();
    }

    // ---- epilogue: two waves share the (now dead) tile smem for staging ----
    float* stg = sm + (warp % MW) * (WM * LDS_T);
    #pragma unroll
    for (int wave = 0; wave < NW; ++wave) {
        if ((warp / MW) == wave) {
            #pragma unroll
            for (int i = 0; i < MI; i++)
                #pragma unroll
                for (int j = 0; j < NI; j++)
                    wmma::store_matrix_sync(&stg[(i * 16) * LDS_T + j * 16], acc[i][j],
                                            LDS_T, wmma::mem_row_major);
            __syncwarp();
            for (int idx = lane; idx < WM * WN; idx += 32) {
                int r  = idx / WN, c2 = idx % WN;
                int gr = bm + wm + r, gc = bn + wn + c2;
                float vv = stg[r * LDS_T + c2];
                if (bias) vv += bias[gc];
                if constexpr (EPI == 1) vv = gelu_f(vv);
                if constexpr (EPI == 2) vv += res[(long long)gr * ldc + gc];
                C[(long long)gr * ldc + gc] = vv;
            }
        }
        __syncthreads();
    }
}

// ---------------- LayerNorm: one row (D=1024) per block, 256 threads ----------
__global__ __launch_bounds__(256)
void ln_kernel(const float* __restrict__ x, const float* __restrict__ g,
               const float* __restrict__ b, float* __restrict__ o)
{
    __shared__ float shs[8], shs2[8], shbc[2];
    const int row = blockIdx.x;
    const float* xr = x + (long long)row * D_;
    float* orow     = o + (long long)row * D_;
    const int t = threadIdx.x;
    float v[4]; float s = 0.f, s2 = 0.f;
    #pragma unroll
    for (int i = 0; i < 4; i++) { v[i] = xr[t + i * 256]; s += v[i]; s2 += v[i] * v[i]; }
    #pragma unroll
    for (int off = 16; off; off >>= 1) {
        s  += __shfl_xor_sync(0xffffffffu, s,  off);
        s2 += __shfl_xor_sync(0xffffffffu, s2, off);
    }
    if ((t & 31) == 0) { shs[t >> 5] = s; shs2[t >> 5] = s2; }
    __syncthreads();
    if (t < 32) {
        s  = (t < 8) ? shs[t]  : 0.f;
        s2 = (t < 8) ? shs2[t] : 0.f;
        #pragma unroll
        for (int off = 4; off; off >>= 1) {
            s  += __shfl_xor_sync(0xffffffffu, s,  off);
            s2 += __shfl_xor_sync(0xffffffffu, s2, off);
        }
        if (t == 0) {
            float mu = s * (1.0f / D_);
            shbc[0] = mu;
            shbc[1] = rsqrtf(s2 * (1.0f / D_) - mu * mu + 1e-5f);
        }
    }
    __syncthreads();
    const float mu = shbc[0], inv = shbc[1];
    #pragma unroll
    for (int i = 0; i < 4; i++) {
        int c = t + i * 256;
        orow[c] = (v[i] - mu) * inv * g[c] + b[c];
    }
}

// ---------------- causal softmax over scores; scale 1/sqrt(64)=0.125 ----------
__global__ __launch_bounds__(256)
void softmax_kernel(float* __restrict__ S)
{
    __shared__ float red[8], bcast;
    const long long row = blockIdx.x;            // b*H*T rows
    const int q = (int)(row % T_);
    float* sr = S + row * (long long)T_;
    const int t = threadIdx.x;
    const int c0 = t * 4;
    float4 vv = *reinterpret_cast<float4*>(sr + c0);
    float val[4];
    val[0] = (c0 + 0 <= q) ? vv.x * 0.125f : -FLT_MAX;
    val[1] = (c0 + 1 <= q) ? vv.y * 0.125f : -FLT_MAX;
    val[2] = (c0 + 2 <= q) ? vv.z * 0.125f : -FLT_MAX;
    val[3] = (c0 + 3 <= q) ? vv.w * 0.125f : -FLT_MAX;
    float mx = fmaxf(fmaxf(val[0], val[1]), fmaxf(val[2], val[3]));
    #pragma unroll
    for (int off = 16; off; off >>= 1) mx = fmaxf(mx, __shfl_xor_sync(0xffffffffu, mx, off));
    if ((t & 31) == 0) red[t >> 5] = mx;
    __syncthreads();
    if (t == 0) {
        float m = red[0];
        #pragma unroll
        for (int i = 1; i < 8; i++) m = fmaxf(m, red[i]);
        bcast = m;
    }
    __syncthreads();
    mx = bcast;
    float e[4], s = 0.f;
    #pragma unroll
    for (int i = 0; i < 4; i++) { e[i] = expf(val[i] - mx); s += e[i]; }
    #pragma unroll
    for (int off = 16; off; off >>= 1) s += __shfl_xor_sync(0xffffffffu, s, off);
    __syncthreads();                 // red[] reuse
    if ((t & 31) == 0) red[t >> 5] = s;
    __syncthreads();
    if (t == 0) {
        float m = 0.f;
        #pragma unroll
        for (int i = 0; i < 8; i++) m += red[i];
        bcast = 1.0f / m;
    }
    __syncthreads();
    const float inv = bcast;
    vv.x = e[0] * inv; vv.y = e[1] * inv; vv.z = e[2] * inv; vv.w = e[3] * inv;
    *reinterpret_cast<float4*>(sr + c0) = vv;
}

// ---------------- embedding ---------------------------------------------------
__global__ __launch_bounds__(256)
void embed_kernel(const int* __restrict__ idx, const float* __restrict__ tok,
                  const float* __restrict__ pos, float* __restrict__ x)
{
    const int bt = blockIdx.x;
    const int tk = idx[bt];
    const int tt = bt % T_;
    const float* tr = tok + (long long)tk * D_;
    const float* pr = pos + (long long)tt * D_;
    float* xr = x + (long long)bt * D_;
    for (int i = threadIdx.x; i < D_; i += 256) xr[i] = tr[i] + pr[i];
}

// ---------------- host-side launcher wrapper ----------------------------------
template<int BM, int BN, int BK, int WM, int WN, bool BT, int EPI>
static void gemm(const float* A, const float* Bm, const float* bias, const float* res,
                 float* C, int M, int N, int K, int lda, int ldb, int ldc,
                 int batch = 1, int innerDiv = 1,
                 long long aO = 0, long long aI = 0,
                 long long bO = 0, long long bI = 0,
                 long long cO = 0, long long cI = 0)
{
    dim3 grid(N / BN, M / BM, batch);
    gemm_kernel<BM, BN, BK, WM, WN, BT, EPI><<<grid, 256>>>(
        A, Bm, bias, res, C, M, N, K, lda, ldb, ldc, innerDiv, aO, aI, bO, bI, cO, cI);
}

extern "C" void kernel_launch(void* const* d_in, const int* in_sizes, int n_in,
                              void* d_out, int out_size)
{
    (void)in_sizes; (void)n_in; (void)out_size;
    const int*   idx   = (const int*)  d_in[0];
    const float* tok   = (const float*)d_in[1];
    const float* pos   = (const float*)d_in[2];
    const float* ln1g  = (const float*)d_in[3];
    const float* ln1b  = (const float*)d_in[4];
    const float* Wq    = (const float*)d_in[5];
    const float* bq    = (const float*)d_in[6];
    const float* Wk    = (const float*)d_in[7];
    const float* bk    = (const float*)d_in[8];
    const float* Wv    = (const float*)d_in[9];
    const float* bv    = (const float*)d_in[10];
    const float* Wo    = (const float*)d_in[11];
    const float* bo    = (const float*)d_in[12];
    const float* ln2g  = (const float*)d_in[13];
    const float* ln2b  = (const float*)d_in[14];
    const float* W1    = (const float*)d_in[15];
    const float* b1    = (const float*)d_in[16];
    const float* W2    = (const float*)d_in[17];
    const float* b2    = (const float*)d_in[18];
    const float* lnfg  = (const float*)d_in[19];
    const float* lnfb  = (const float*)d_in[20];
    const float* Wh    = (const float*)d_in[21];
    const float* bh    = (const float*)d_in[22];

    float *x, *h, *q, *k, *v, *o, *ff, *s;
    cudaGetSymbolAddress((void**)&x,  g_x);
    cudaGetSymbolAddress((void**)&h,  g_h);
    cudaGetSymbolAddress((void**)&q,  g_q);
    cudaGetSymbolAddress((void**)&k,  g_k);
    cudaGetSymbolAddress((void**)&v,  g_v);
    cudaGetSymbolAddress((void**)&o,  g_o);
    cudaGetSymbolAddress((void**)&ff, g_ff);
    cudaGetSymbolAddress((void**)&s,  g_s);

    embed_kernel<<<M_, 256>>>(idx, tok, pos, x);

    for (int l = 0; l < L_; ++l) {
        const float* Wq_l = Wq + (size_t)l * D_ * D_;
        const float* Wk_l = Wk + (size_t)l * D_ * D_;
        const float* Wv_l = Wv + (size_t)l * D_ * D_;
        const float* Wo_l = Wo + (size_t)l * D_ * D_;
        const float* W1_l = W1 + (size_t)l * D_ * FF_;
        const float* W2_l = W2 + (size_t)l * FF_ * D_;

        // ln1 -> h
        ln_kernel<<<M_, 256>>>(x, ln1g + (size_t)l * D_, ln1b + (size_t)l * D_, h);

        // q, k, v projections
        gemm<128,128,32,32,64,false,0>(h, Wq_l, bq + (size_t)l * D_, nullptr, q, M_, D_, D_, D_, D_, D_);
        gemm<128,128,32,32,64,false,0>(h, Wk_l, bk + (size_t)l * D_, nullptr, k, M_, D_, D_, D_, D_, D_);
        gemm<128,128,32,32,64,false,0>(h, Wv_l, bv + (size_t)l * D_, nullptr, v, M_, D_, D_, D_, D_, D_);

        // scores S[b,h] = Q_bh @ K_bh^T   (batched NT, K=DH)
        gemm<128,128,32,32,64,true,0>(q, k, nullptr, nullptr, s,
            T_, T_, DH_, D_, D_, T_,
            B_ * H_, H_,
            (long long)T_ * D_, (long long)DH_,
            (long long)T_ * D_, (long long)DH_,
            (long long)H_ * T_ * T_, (long long)T_ * T_);

        // causal softmax in-place
        softmax_kernel<<<B_ * H_ * T_, 256>>>(s);

        // O[b,h] = P @ V_bh  (batched NN, N=DH)
        gemm<128,64,32,32,32,false,0>(s, v, nullptr, nullptr, o,
            T_, DH_, T_, T_, D_, D_,
            B_ * H_, H_,
            (long long)H_ * T_ * T_, (long long)T_ * T_,
            (long long)T_ * D_, (long long)DH_,
            (long long)T_ * D_, (long long)DH_);

        // x = x + O @ Wo + bo
        gemm<128,128,32,32,64,false,2>(o, Wo_l, bo + (size_t)l * D_, x, x, M_, D_, D_, D_, D_, D_);

        // ln2 -> h
        ln_kernel<<<M_, 256>>>(x, ln2g + (size_t)l * D_, ln2b + (size_t)l * D_, h);

        // ff = gelu(h @ W1 + b1)
        gemm<128,128,32,32,64,false,1>(h, W1_l, b1 + (size_t)l * FF_, nullptr, ff, M_, FF_, D_, D_, FF_, FF_);

        // x = x + ff @ W2 + b2
        gemm<128,128,32,32,64,false,2>(ff, W2_l, b2 + (size_t)l * D_, x, x, M_, D_, FF_, FF_, D_, D_);
    }

    // final LN + head
    ln_kernel<<<M_, 256>>>(x, lnfg, lnfb, h);
    gemm<128,128,32,32,64,false,0>(h, Wh, bh, nullptr, (float*)d_out, M_, V_, D_, D_, V_, V_);
}